// round 10
// baseline (speedup 1.0000x reference)
#include <cuda_runtime.h>
#include <cuda_fp16.h>
#include <cuda_bf16.h>
#include <mma.h>

using namespace nvcuda;

// ---------------- problem-size constants (scratch sized to these) ----------
#define MAXN 100352            // >= 100000 nodes
#define MAXE 1703936           // >= 1600000 edges
#define MAXG 1024              // >= 1000 graphs
#define F1 64
#define F2 32
#define ELLW 64                // slots per node; P(in-deg >= 64) ~ 2e-18

// ---------------- static device scratch (no allocations allowed) ----------
static __device__ float  d_degw[MAXN];
static __device__ int    d_cnt[MAXN];
static __device__ float  d_dinv[MAXN];
static __device__ int2   d_ell[(size_t)MAXN * ELLW];  // {src, edge_weight bits}
static __device__ __half d_m0[MAXN * F1];    // dinv .* (x @ W0)      [N,64]
static __device__ __half d_m1[MAXN * F2];    // dinv .* (h0 @ W1)     [N,32]
static __device__ float  d_g [MAXG * F2];    // pooled                [G,32]

// ---------------- small utility kernels -----------------------------------
__global__ void k_zero(int n, int gsz) {
    int i = blockIdx.x * blockDim.x + threadIdx.x;
    if (i < n) { d_degw[i] = 0.f; d_cnt[i] = 0; }
    if (i < gsz) d_g[i] = 0.f;
}

__global__ void k_deg(const int* __restrict__ dst,
                      const float* __restrict__ w, int E) {
    int e = blockIdx.x * blockDim.x + threadIdx.x;
    if (e >= E) return;
    atomicAdd(&d_degw[dst[e]], w[e]);
}

__global__ void k_dinv(int n) {
    int i = blockIdx.x * blockDim.x + threadIdx.x;
    if (i >= n) return;
    float deg = d_degw[i] + 1.0f;            // + self-loop weight
    d_dinv[i] = (deg > 0.f) ? rsqrtf(fmaxf(deg, 1e-12f)) : 0.f;
}

// ---------------- ELL fill: {src, raw weight} at atomic slot ---------------
__global__ void k_fill(const int* __restrict__ src, const int* __restrict__ dst,
                       const float* __restrict__ w, int E) {
    int e = blockIdx.x * blockDim.x + threadIdx.x;
    if (e >= E) return;
    int d = dst[e];
    int2 pk; pk.x = src[e]; pk.y = __float_as_int(w[e]);
    int slot = atomicAdd(&d_cnt[d], 1);
    if (slot < ELLW) d_ell[(size_t)d * ELLW + slot] = pk;
}

// ---------------- GEMM0: m0 = dinv .* (x @ W0)  (fp16 out) -----------------
__global__ void __launch_bounds__(256) k_gemm0(const float* __restrict__ x,
                                               const float* __restrict__ W, int n) {
    __shared__ __align__(16) char sm[64 * 136 * 2 + 128 * 72 * 2];
    __shared__ float sdv[64];
    __half (*xs)[136] = reinterpret_cast<__half(*)[136]>(sm);
    __half (*ws)[72]  = reinterpret_cast<__half(*)[72]>(sm + 64 * 136 * 2);
    float  (*os)[68]  = reinterpret_cast<float(*)[68]>(sm);      // aliases xs

    int tid = threadIdx.x;
    int rowBase = blockIdx.x * 64;

    if (tid < 64) {
        int grow = rowBase + tid;
        sdv[tid] = (grow < n) ? d_dinv[grow] : 0.f;
    }
#pragma unroll
    for (int it = 0; it < 8; it++) {
        int idx = tid + it * 256;
        int r = idx >> 5, c = idx & 31;
        float4 v = make_float4(0.f, 0.f, 0.f, 0.f);
        int grow = rowBase + r;
        if (grow < n) v = *reinterpret_cast<const float4*>(x + (size_t)grow * 128 + c * 4);
        __half2 h0 = __floats2half2_rn(v.x, v.y);
        __half2 h1 = __floats2half2_rn(v.z, v.w);
        uint2 u; u.x = *reinterpret_cast<unsigned*>(&h0); u.y = *reinterpret_cast<unsigned*>(&h1);
        *reinterpret_cast<uint2*>(&xs[r][c * 4]) = u;
    }
#pragma unroll
    for (int it = 0; it < 8; it++) {
        int idx = tid + it * 256;
        int r = idx >> 4, c = idx & 15;
        float4 v = *reinterpret_cast<const float4*>(W + (size_t)r * 64 + c * 4);
        __half2 h0 = __floats2half2_rn(v.x, v.y);
        __half2 h1 = __floats2half2_rn(v.z, v.w);
        uint2 u; u.x = *reinterpret_cast<unsigned*>(&h0); u.y = *reinterpret_cast<unsigned*>(&h1);
        *reinterpret_cast<uint2*>(&ws[r][c * 4]) = u;
    }
    __syncthreads();

    int warp = tid >> 5;
    int rb = warp >> 1;          // 0..3 : row block (16 rows)
    int ch = warp & 1;           // 0..1 : column half (32 cols)

    wmma::fragment<wmma::accumulator, 16, 16, 16, float> c0, c1;
    wmma::fill_fragment(c0, 0.f);
    wmma::fill_fragment(c1, 0.f);
#pragma unroll
    for (int k = 0; k < 8; k++) {
        wmma::fragment<wmma::matrix_a, 16, 16, 16, __half, wmma::row_major> a;
        wmma::load_matrix_sync(a, &xs[rb * 16][k * 16], 136);
        wmma::fragment<wmma::matrix_b, 16, 16, 16, __half, wmma::row_major> b0, b1;
        wmma::load_matrix_sync(b0, &ws[k * 16][ch * 32], 72);
        wmma::load_matrix_sync(b1, &ws[k * 16][ch * 32 + 16], 72);
        wmma::mma_sync(c0, a, b0, c0);
        wmma::mma_sync(c1, a, b1, c1);
    }
    __syncthreads();             // xs no longer needed; reuse as float out
    wmma::store_matrix_sync(&os[rb * 16][ch * 32], c0, 68, wmma::mem_row_major);
    wmma::store_matrix_sync(&os[rb * 16][ch * 32 + 16], c1, 68, wmma::mem_row_major);
    __syncthreads();

#pragma unroll
    for (int it = 0; it < 8; it++) {
        int idx = tid + it * 256;
        int r = idx >> 5, c2 = idx & 31;
        int grow = rowBase + r;
        if (grow < n) {
            float dv = sdv[r];
            __half2 h = __floats2half2_rn(os[r][c2 * 2] * dv, os[r][c2 * 2 + 1] * dv);
            reinterpret_cast<__half2*>(d_m0 + (size_t)grow * 64)[c2] = h;
        }
    }
}

// ------- fused agg0 + GEMM1: m1 = dinv .* (relu(agg+b0) @ W1)  fp16 --------
// h[d] = relu(dinv[d]*(sum_e ew*m0[src] + m0[d]) + b0)   (m0 pre-scaled)
__global__ void __launch_bounds__(512) k_agg0_gemm1(const float* __restrict__ b0,
                                                    const float* __restrict__ W, int n) {
    __shared__ __align__(16) char sm[64 * 72 * 2 + 64 * 40 * 2];
    __shared__ float sdv[64];
    __half (*xs)[72] = reinterpret_cast<__half(*)[72]>(sm);
    __half (*ws)[40] = reinterpret_cast<__half(*)[40]>(sm + 64 * 72 * 2);
    float  (*os)[36] = reinterpret_cast<float(*)[36]>(sm);       // aliases xs

    int tid = threadIdx.x;
    int base = blockIdx.x * 64;
    int warp = tid >> 5;
    int lane = tid & 31;

    if (tid < 64) {
        int grow = base + tid;
        sdv[tid] = (grow < n) ? d_dinv[grow] : 0.f;
    }
    // load W1 [64,32] fp32 -> fp16 : 512 float4 jobs, one per thread
    {
        int r = tid >> 3, c = tid & 7;
        float4 v = *reinterpret_cast<const float4*>(W + (size_t)r * 32 + c * 4);
        __half2 h0 = __floats2half2_rn(v.x, v.y);
        __half2 h1 = __floats2half2_rn(v.z, v.w);
        uint2 u; u.x = *reinterpret_cast<unsigned*>(&h0); u.y = *reinterpret_cast<unsigned*>(&h1);
        *reinterpret_cast<uint2*>(&ws[r][c * 4]) = u;
    }
    __syncthreads();

    // aggregate 4 nodes per warp into xs rows
    const __half2* m = reinterpret_cast<const __half2*>(d_m0);
    float bx = b0[2 * lane], by = b0[2 * lane + 1];
#pragma unroll
    for (int i = 0; i < 4; i++) {
        int node = base + warp * 4 + i;
        int row = warp * 4 + i;
        if (node < n) {
            float2 mm = __half22float2(m[(size_t)node * 32 + lane]);
            float ax = mm.x, ay = mm.y;          // self term (pre-scaled m0)
            const int2* ell = d_ell + (size_t)node * ELLW;
            int cnt = d_cnt[node]; if (cnt > ELLW) cnt = ELLW;
            int e = 0;
            for (; e + 4 <= cnt; e += 4) {
                int2 p0 = ell[e], p1 = ell[e + 1], p2 = ell[e + 2], p3 = ell[e + 3];
                float2 v0 = __half22float2(m[(size_t)p0.x * 32 + lane]);
                float2 v1 = __half22float2(m[(size_t)p1.x * 32 + lane]);
                float2 v2 = __half22float2(m[(size_t)p2.x * 32 + lane]);
                float2 v3 = __half22float2(m[(size_t)p3.x * 32 + lane]);
                float w0 = __int_as_float(p0.y), w1 = __int_as_float(p1.y);
                float w2 = __int_as_float(p2.y), w3 = __int_as_float(p3.y);
                ax += w0 * v0.x; ay += w0 * v0.y;
                ax += w1 * v1.x; ay += w1 * v1.y;
                ax += w2 * v2.x; ay += w2 * v2.y;
                ax += w3 * v3.x; ay += w3 * v3.y;
            }
            for (; e < cnt; e++) {
                int2 p = ell[e];
                float2 v = __half22float2(m[(size_t)p.x * 32 + lane]);
                float w = __int_as_float(p.y);
                ax += w * v.x; ay += w * v.y;
            }
            float dv = sdv[row];
            ax = fmaxf(ax * dv + bx, 0.f); ay = fmaxf(ay * dv + by, 0.f);
            *reinterpret_cast<__half2*>(&xs[row][lane * 2]) = __floats2half2_rn(ax, ay);
        } else {
            *reinterpret_cast<__half2*>(&xs[row][lane * 2]) = __half2half2(__float2half(0.f));
        }
    }
    __syncthreads();

    // wmma: warps 0..7, each computes one 16x16 block of the 64x32 output
    if (warp < 8) {
        int rb = warp >> 1;      // 0..3
        int cb = warp & 1;       // 0..1
        wmma::fragment<wmma::accumulator, 16, 16, 16, float> c0;
        wmma::fill_fragment(c0, 0.f);
#pragma unroll
        for (int k = 0; k < 4; k++) {
            wmma::fragment<wmma::matrix_a, 16, 16, 16, __half, wmma::row_major> a;
            wmma::load_matrix_sync(a, &xs[rb * 16][k * 16], 72);
            wmma::fragment<wmma::matrix_b, 16, 16, 16, __half, wmma::row_major> b;
            wmma::load_matrix_sync(b, &ws[k * 16][cb * 16], 40);
            wmma::mma_sync(c0, a, b, c0);
        }
        __syncthreads();         // all mma reads of xs done
        wmma::store_matrix_sync(&os[rb * 16][cb * 16], c0, 36, wmma::mem_row_major);
    } else {
        __syncthreads();
    }
    __syncthreads();

    // write out m1 = dinv .* os, fp16 : 64 rows x 16 half2 = 1024 jobs
#pragma unroll
    for (int it = 0; it < 2; it++) {
        int idx = tid + it * 512;
        int r = idx >> 4, c2 = idx & 15;
        int grow = base + r;
        if (grow < n) {
            float dv = sdv[r];
            __half2 h = __floats2half2_rn(os[r][c2 * 2] * dv, os[r][c2 * 2 + 1] * dv);
            reinterpret_cast<__half2*>(d_m1 + (size_t)grow * 32)[c2] = h;
        }
    }
}

// ---------------- agg1 + pooling: g[graph] += relu(agg + b1) ---------------
__global__ void __launch_bounds__(256) k_agg1(const float* __restrict__ b1,
                                              const int* __restrict__ ngi, int n) {
    int warp = (blockIdx.x * blockDim.x + threadIdx.x) >> 5;
    int lane = threadIdx.x & 31;
    if (warp >= n) return;
    float acc = __half2float(d_m1[(size_t)warp * 32 + lane]);   // self (pre-scaled)
    const int2* ell = d_ell + (size_t)warp * ELLW;
    int cnt = d_cnt[warp]; if (cnt > ELLW) cnt = ELLW;
    int e = 0;
    for (; e + 4 <= cnt; e += 4) {
        int2 p0 = ell[e], p1 = ell[e + 1], p2 = ell[e + 2], p3 = ell[e + 3];
        acc += __int_as_float(p0.y) * __half2float(d_m1[(size_t)p0.x * 32 + lane]);
        acc += __int_as_float(p1.y) * __half2float(d_m1[(size_t)p1.x * 32 + lane]);
        acc += __int_as_float(p2.y) * __half2float(d_m1[(size_t)p2.x * 32 + lane]);
        acc += __int_as_float(p3.y) * __half2float(d_m1[(size_t)p3.x * 32 + lane]);
    }
    for (; e < cnt; e++) {
        int2 p = ell[e];
        acc += __int_as_float(p.y) * __half2float(d_m1[(size_t)p.x * 32 + lane]);
    }
    float h = fmaxf(acc * d_dinv[warp] + b1[lane], 0.f);
    int g = ngi[warp];
    atomicAdd(&d_g[(size_t)g * 32 + lane], h);
}

// ---------------- MLP head: logits = relu(g@Wm1+bm1)@Wm2+bm2 ---------------
__global__ void __launch_bounds__(128) k_mlp(const float* __restrict__ Wm1,
                                             const float* __restrict__ bm1,
                                             const float* __restrict__ Wm2,
                                             const float* __restrict__ bm2,
                                             float* __restrict__ out, int G) {
    int gi = blockIdx.x;
    if (gi >= G) return;
    __shared__ float gs[32];
    __shared__ float red0[4], red1[4];
    int t = threadIdx.x;
    if (t < 32) gs[t] = d_g[(size_t)gi * 32 + t];
    __syncthreads();
    float acc = bm1[t];
#pragma unroll
    for (int k = 0; k < 32; k++) acc += gs[k] * Wm1[k * 128 + t];
    float h = fmaxf(acc, 0.f);
    float p0 = h * Wm2[t * 2 + 0];
    float p1 = h * Wm2[t * 2 + 1];
#pragma unroll
    for (int off = 16; off > 0; off >>= 1) {
        p0 += __shfl_down_sync(0xffffffffu, p0, off);
        p1 += __shfl_down_sync(0xffffffffu, p1, off);
    }
    if ((t & 31) == 0) { red0[t >> 5] = p0; red1[t >> 5] = p1; }
    __syncthreads();
    if (t == 0) {
        out[gi * 2 + 0] = red0[0] + red0[1] + red0[2] + red0[3] + bm2[0];
        out[gi * 2 + 1] = red1[0] + red1[1] + red1[2] + red1[3] + bm2[1];
    }
}

// ---------------------------------------------------------------------------
extern "C" void kernel_launch(void* const* d_in, const int* in_sizes, int n_in,
                              void* d_out, int out_size) {
    const float* x   = (const float*)d_in[0];
    const int*   ei  = (const int*)d_in[1];
    const float* ew  = (const float*)d_in[2];
    const int*   ngi = (const int*)d_in[3];
    const float* W0  = (const float*)d_in[4];
    const float* b0  = (const float*)d_in[5];
    const float* W1  = (const float*)d_in[6];
    const float* b1  = (const float*)d_in[7];
    const float* Wm1 = (const float*)d_in[8];
    const float* bm1 = (const float*)d_in[9];
    const float* Wm2 = (const float*)d_in[10];
    const float* bm2 = (const float*)d_in[11];
    float* out = (float*)d_out;

    int N = in_sizes[3];            // node_graph_index count
    int E = in_sizes[1] / 2;        // edge_index is [2, E]
    int G = out_size / 2;
    if (N > MAXN) N = MAXN;
    if (E > MAXE) E = MAXE;
    if (G > MAXG) G = MAXG;

    const int* e_src = ei;
    const int* e_dst = ei + E;

    // one-time side-stream + events (created outside any capture; reused in it)
    static cudaStream_t s_aux = nullptr;
    static cudaEvent_t  s_fork = nullptr, s_join = nullptr;
    if (s_aux == nullptr) {
        cudaStreamCreateWithFlags(&s_aux, cudaStreamNonBlocking);
        cudaEventCreateWithFlags(&s_fork, cudaEventDisableTiming);
        cudaEventCreateWithFlags(&s_join, cudaEventDisableTiming);
    }

    // degree + dinv (no scan needed with ELL)
    k_zero<<<(N + 255) / 256, 256>>>(N, G * 32);                    // 0
    k_deg<<<(E + 255) / 256, 256>>>(e_dst, ew, E);                  // 1
    k_dinv<<<(N + 255) / 256, 256>>>(N);                            // 2

    // fork: gemm0 (needs dinv) overlaps with ELL fill
    cudaEventRecord(s_fork, 0);
    cudaStreamWaitEvent(s_aux, s_fork, 0);
    k_gemm0<<<(N + 63) / 64, 256, 0, s_aux>>>(x, W0, N);            // 3
    cudaEventRecord(s_join, s_aux);

    k_fill<<<(E + 255) / 256, 256>>>(e_src, e_dst, ew, E);          // 4

    // join, then fused layer-1-agg + layer-2-GEMM, agg1+pool, MLP head
    cudaStreamWaitEvent(0, s_join, 0);
    k_agg0_gemm1<<<(N + 63) / 64, 512>>>(b0, W1, N);                // 5 <- ncu -s 5
    k_agg1<<<(N + 7) / 8, 256>>>(b1, ngi, N);                       // 6
    k_mlp<<<G, 128>>>(Wm1, bm1, Wm2, bm2, out, G);                  // 7
}